// round 1
// baseline (speedup 1.0000x reference)
#include <cuda_runtime.h>
#include <stdint.h>

#define NCOMP 256
#define PPB   4   // pairs per block

// Bit-packed sign table: g_signtab[ihi*256 + j], bit L = 1 iff sign(j, j ^ (ihi*32+L)) == -1
__device__ uint32_t g_signtab[8 * 256];

__global__ void build_sign_table_kernel() {
    int t    = blockIdx.x * blockDim.x + threadIdx.x;   // 0..65535
    int lane = t & 31;
    int j    = (t >> 5) & 255;
    int ihi  = t >> 13;
    int i    = (ihi << 5) | lane;
    int k    = j ^ i;
    int par  = 0;
#pragma unroll
    for (int d = 1; d < 8; ++d) par ^= __popc((j >> d) & k);
    unsigned w = __ballot_sync(0xFFFFFFFFu, par & 1);
    if (lane == 0) g_signtab[(ihi << 8) + j] = w;
}

__global__ __launch_bounds__(256, 2) void clifford_kernel(
    const float* __restrict__ A, const float* __restrict__ B,
    float* __restrict__ out, int npairs)
{
    __shared__ float    Ash[PPB * NCOMP];
    __shared__ float    Bsh[PPB * NCOMP];
    __shared__ uint32_t Ush[8 * 256];

    const int tid = threadIdx.x;
    const int p0  = blockIdx.x * PPB;

    // Stage A/B rows (4 pairs = 4 KB each) and the 8 KB sign table into smem.
    reinterpret_cast<float4*>(Ash)[tid] =
        reinterpret_cast<const float4*>(A + (size_t)p0 * NCOMP)[tid];
    reinterpret_cast<float4*>(Bsh)[tid] =
        reinterpret_cast<const float4*>(B + (size_t)p0 * NCOMP)[tid];
    reinterpret_cast<uint4*>(Ush)[tid]       = reinterpret_cast<const uint4*>(g_signtab)[tid];
    reinterpret_cast<uint4*>(Ush)[tid + 256] = reinterpret_cast<const uint4*>(g_signtab)[tid + 256];
    __syncthreads();

    const int i     = tid;          // output component owned by this thread
    const int lane  = tid & 31;
    const int shamt = 31 - lane;    // loop-invariant shift to park our sign bit at bit 31
    const int notI  = (~i) & 255;
    const uint32_t* __restrict__ Urow = Ush + ((tid >> 5) << 8);

    float ag0 = 0.f, ag1 = 0.f, ag2 = 0.f, ag3 = 0.f;   // geometric
    float aw0 = 0.f, aw1 = 0.f, aw2 = 0.f, aw3 = 0.f;   // wedge
    float ai0 = 0.f, ai1 = 0.f, ai2 = 0.f, ai3 = 0.f;   // inner

#pragma unroll 2
    for (int j4 = 0; j4 < NCOMP / 4; ++j4) {
        const int j = j4 << 2;
        const uint4  sw4 = *reinterpret_cast<const uint4*>(Urow + j);
        const float4 a0  = *reinterpret_cast<const float4*>(Ash + 0 * NCOMP + j);
        const float4 a1  = *reinterpret_cast<const float4*>(Ash + 1 * NCOMP + j);
        const float4 a2  = *reinterpret_cast<const float4*>(Ash + 2 * NCOMP + j);
        const float4 a3  = *reinterpret_cast<const float4*>(Ash + 3 * NCOMP + j);

#define DO_J(JOFF, SWV, A0V, A1V, A2V, A3V)                                        \
        {                                                                          \
            const int      jj  = j + (JOFF);                                       \
            const uint32_t sm  = ((SWV) << shamt) & 0x80000000u;                   \
            const bool     wed = ((jj & notI) == 0);              /* j subset i */ \
            const bool     inn = (((jj & i) == 0) | ((i & ~jj) == 0));             \
            const int      kx  = jj ^ i;                                           \
            {                                                                      \
                float b  = Bsh[0 * NCOMP + kx];                                    \
                float bs = __uint_as_float(__float_as_uint(b) ^ sm);               \
                ag0 = fmaf((A0V), bs, ag0);                                        \
                if (wed) aw0 = fmaf((A0V), bs, aw0);                               \
                if (inn) ai0 = fmaf((A0V), bs, ai0);                               \
            }                                                                      \
            {                                                                      \
                float b  = Bsh[1 * NCOMP + kx];                                    \
                float bs = __uint_as_float(__float_as_uint(b) ^ sm);               \
                ag1 = fmaf((A1V), bs, ag1);                                        \
                if (wed) aw1 = fmaf((A1V), bs, aw1);                               \
                if (inn) ai1 = fmaf((A1V), bs, ai1);                               \
            }                                                                      \
            {                                                                      \
                float b  = Bsh[2 * NCOMP + kx];                                    \
                float bs = __uint_as_float(__float_as_uint(b) ^ sm);               \
                ag2 = fmaf((A2V), bs, ag2);                                        \
                if (wed) aw2 = fmaf((A2V), bs, aw2);                               \
                if (inn) ai2 = fmaf((A2V), bs, ai2);                               \
            }                                                                      \
            {                                                                      \
                float b  = Bsh[3 * NCOMP + kx];                                    \
                float bs = __uint_as_float(__float_as_uint(b) ^ sm);               \
                ag3 = fmaf((A3V), bs, ag3);                                        \
                if (wed) aw3 = fmaf((A3V), bs, aw3);                               \
                if (inn) ai3 = fmaf((A3V), bs, ai3);                               \
            }                                                                      \
        }

        DO_J(0, sw4.x, a0.x, a1.x, a2.x, a3.x);
        DO_J(1, sw4.y, a0.y, a1.y, a2.y, a3.y);
        DO_J(2, sw4.z, a0.z, a1.z, a2.z, a3.z);
        DO_J(3, sw4.w, a0.w, a1.w, a2.w, a3.w);
#undef DO_J
    }

    // out layout: [3, npairs, NCOMP]
    const size_t plane = (size_t)npairs * NCOMP;
    float* __restrict__ og = out + (size_t)p0 * NCOMP + i;
    float* __restrict__ ow = og + plane;
    float* __restrict__ oi = og + 2 * plane;

    og[0 * NCOMP] = ag0; og[1 * NCOMP] = ag1; og[2 * NCOMP] = ag2; og[3 * NCOMP] = ag3;
    ow[0 * NCOMP] = aw0; ow[1 * NCOMP] = aw1; ow[2 * NCOMP] = aw2; ow[3 * NCOMP] = aw3;
    oi[0 * NCOMP] = ai0; oi[1 * NCOMP] = ai1; oi[2 * NCOMP] = ai2; oi[3 * NCOMP] = ai3;
}

extern "C" void kernel_launch(void* const* d_in, const int* in_sizes, int n_in,
                              void* d_out, int out_size)
{
    const float* A = (const float*)d_in[0];
    const float* B = (const float*)d_in[1];
    float* out = (float*)d_out;

    const int npairs = in_sizes[0] / NCOMP;   // 4*256 = 1024

    // Rebuild the bit-packed sign table every call (deterministic, ~<1us).
    build_sign_table_kernel<<<256, 256>>>();

    clifford_kernel<<<npairs / PPB, 256>>>(A, B, out, npairs);
}